// round 16
// baseline (speedup 1.0000x reference)
#include <cuda_runtime.h>
#include <cuda_bf16.h>
#include <cuda_fp16.h>
#include <cstdint>

// Problem constants (fixed by the reference)
#define NN      10000
#define KNN     32
#define DG      256
#define ODIM    256
#define XSTRIDE 512   // 2*DG

// Scratch: fp16 transformed feature table + fp16 W
__device__ __half g_hh[NN * XSTRIDE];
__device__ __half g_Wh[2 * ODIM * DG];

__device__ __forceinline__ uint32_t smem_u32(const void* p) {
    uint32_t a;
    asm("{ .reg .u64 t; cvta.to.shared.u64 t, %1; cvt.u32.u64 %0, t; }"
        : "=r"(a) : "l"(p));
    return a;
}

__device__ __forceinline__ void ldm_x4(uint32_t* r, uint32_t addr) {
    asm volatile("ldmatrix.sync.aligned.m8n8.x4.shared.b16 {%0,%1,%2,%3}, [%4];"
                 : "=r"(r[0]), "=r"(r[1]), "=r"(r[2]), "=r"(r[3]) : "r"(addr));
}

__device__ __forceinline__ void mma_fp16(float* d, const uint32_t* a,
                                         const uint32_t* b) {
    asm volatile(
        "mma.sync.aligned.m16n8k16.row.col.f32.f16.f16.f32 "
        "{%0,%1,%2,%3}, {%4,%5,%6,%7}, {%8,%9}, {%0,%1,%2,%3};"
        : "+f"(d[0]), "+f"(d[1]), "+f"(d[2]), "+f"(d[3])
        : "r"(a[0]), "r"(a[1]), "r"(a[2]), "r"(a[3]), "r"(b[0]), "r"(b[1]));
}

__device__ __forceinline__ void cp_async16(uint32_t smem, const void* gptr) {
    asm volatile("cp.async.cg.shared.global [%0], [%1], 16;"
                 :: "r"(smem), "l"(gptr) : "memory");
}
__device__ __forceinline__ void cp_commit() {
    asm volatile("cp.async.commit_group;" ::: "memory");
}
__device__ __forceinline__ void cp_wait0() {
    asm volatile("cp.async.wait_group 0;" ::: "memory");
}

// unpack 8 halves (uint4) into 8 floats
__device__ __forceinline__ void h8_to_f8(uint4 u, float* f) {
    float2 p;
    p = __half22float2(*(__half2*)&u.x); f[0] = p.x; f[1] = p.y;
    p = __half22float2(*(__half2*)&u.y); f[2] = p.x; f[3] = p.y;
    p = __half22float2(*(__half2*)&u.z); f[4] = p.x; f[5] = p.y;
    p = __half22float2(*(__half2*)&u.w); f[6] = p.x; f[7] = p.y;
}

// ---------------------------------------------------------------------------
// Kernel 0: convert W1/W2 to fp16.
// ---------------------------------------------------------------------------
__global__ __launch_bounds__(256)
void wcvt_kernel(const float* __restrict__ W1, const float* __restrict__ W2) {
    int idx = blockIdx.x * 256 + threadIdx.x;
    int wlin = idx * 4;
    int g = wlin >= ODIM * DG;
    int off = wlin - g * ODIM * DG;
    const float* __restrict__ W = g ? W2 : W1;
    float4 v = *(const float4*)&W[off];
    __half2 p0 = __floats2half2_rn(v.x, v.y);
    __half2 p1 = __floats2half2_rn(v.z, v.w);
    *(uint2*)&g_Wh[wlin] = make_uint2(*(uint32_t*)&p0, *(uint32_t*)&p1);
}

// ---------------------------------------------------------------------------
// GEMM via HMMA fp16 (proven R13): 64x256 tile, software-pipelined fills,
// 8 warps (2m x 4n). Grid (157, 2). Epilogue -> fp16 table.
// ---------------------------------------------------------------------------
#define STR 40   // fp16 per smem row (32 k + 8 pad): 80B stride, conflict-free

#define ABUF      (64 * STR * 2)                 // 5120
#define BBUF      (256 * STR * 2)                // 20480
#define DSM_A     0                               // 2 x ABUF
#define DSM_B     (2 * ABUF)                      // 10240, 2 x BBUF
#define DSM_FW    (DSM_B + 2 * BBUF)              // 51200
#define DSM_RED   (DSM_FW + 1024)                 // 52224
#define DSM_TOTAL (DSM_RED + 1024)                // 53248

__global__ __launch_bounds__(256)
void gemm_mma_kernel(const float* __restrict__ x,
                     const float* __restrict__ a1, const float* __restrict__ a2) {
    extern __shared__ char dsm[];
    float* sFW = (float*)(dsm + DSM_FW);
    float* red = (float*)(dsm + DSM_RED);

    const int t    = threadIdx.x;
    const int lane = t & 31;
    const int wid  = t >> 5;
    const int wm   = wid >> 2;     // 0..1
    const int wn   = wid & 3;      // 0..3
    const int g    = blockIdx.y;
    const int i0   = blockIdx.x * 64;
    const float* __restrict__ a = g ? a2 : a1;
    const __half* __restrict__ Wh = g_Wh + g * ODIM * DG;

    // ---- fused fw = softmax(a) ----
    float av = a[t];
    red[t] = av; __syncthreads();
    #pragma unroll
    for (int s = 128; s > 0; s >>= 1) {
        if (t < s) red[t] = fmaxf(red[t], red[t + s]);
        __syncthreads();
    }
    float amax = red[0]; __syncthreads();
    float e = expf(av - amax);
    red[t] = e; __syncthreads();
    #pragma unroll
    for (int s = 128; s > 0; s >>= 1) {
        if (t < s) red[t] += red[t + s];
        __syncthreads();
    }
    float esum = red[0]; __syncthreads();
    sFW[t] = e / esum;

    const uint32_t sAb = smem_u32(dsm + DSM_A);
    const uint32_t sBb = smem_u32(dsm + DSM_B);
    const uint32_t aoff = (uint32_t)(((wm * 32 + (lane & 15)) * STR +
                                      ((lane >> 4) & 1) * 8) * 2);
    const uint32_t boff = (uint32_t)(((wn * 64 + (lane & 7) + ((lane >> 4) & 1) * 8) * STR +
                                      ((lane >> 3) & 1) * 8) * 2);

    float acc[2][8][4];
    #pragma unroll
    for (int mt = 0; mt < 2; ++mt)
        #pragma unroll
        for (int nt = 0; nt < 8; ++nt)
            #pragma unroll
            for (int q = 0; q < 4; ++q) acc[mt][nt][q] = 0.f;

    const int arow = t >> 2;
    const int akk  = (t & 3) * 8;
    const bool arow_ok = (i0 + arow) < NN;
    const float* __restrict__ xrow =
        x + (size_t)(i0 + arow) * XSTRIDE + g * DG + akk;
    const uint32_t aSts = (uint32_t)((arow * STR + akk) * 2);

    int brow[4], bkk[4];
    #pragma unroll
    for (int q = 0; q < 4; ++q) {
        int lin = q * 256 + t;
        brow[q] = lin >> 2;
        bkk[q]  = (lin & 3) * 8;
    }

    // ---- prologue: stage chunk 0 ----
    {
        #pragma unroll
        for (int q = 0; q < 4; ++q)
            cp_async16(sBb + (uint32_t)((brow[q] * STR + bkk[q]) * 2),
                       &Wh[(size_t)brow[q] * DG + bkk[q]]);
        cp_commit();
        float4 v0 = make_float4(0.f, 0.f, 0.f, 0.f);
        float4 v1 = make_float4(0.f, 0.f, 0.f, 0.f);
        if (arow_ok) {
            v0 = *(const float4*)(xrow);
            v1 = *(const float4*)(xrow + 4);
        }
        __half2 p0 = __floats2half2_rn(v0.x, v0.y);
        __half2 p1 = __floats2half2_rn(v0.z, v0.w);
        __half2 p2 = __floats2half2_rn(v1.x, v1.y);
        __half2 p3 = __floats2half2_rn(v1.z, v1.w);
        *(uint4*)(dsm + aSts) = make_uint4(
            *(uint32_t*)&p0, *(uint32_t*)&p1, *(uint32_t*)&p2, *(uint32_t*)&p3);
        cp_wait0();
    }
    __syncthreads();

    for (int c = 0; c < 8; ++c) {
        const int buf  = c & 1;
        const int nbuf = buf ^ 1;
        const bool pf = c < 7;
        float4 v0, v1;

        if (pf) {
            const int kn = (c + 1) * 32;
            #pragma unroll
            for (int q = 0; q < 4; ++q)
                cp_async16(sBb + (uint32_t)(nbuf * BBUF + (brow[q] * STR + bkk[q]) * 2),
                           &Wh[(size_t)brow[q] * DG + kn + bkk[q]]);
            cp_commit();
            if (arow_ok) {
                v0 = *(const float4*)(xrow + kn);
                v1 = *(const float4*)(xrow + kn + 4);
            } else {
                v0 = make_float4(0.f, 0.f, 0.f, 0.f);
                v1 = make_float4(0.f, 0.f, 0.f, 0.f);
            }
        }

        const uint32_t sA0 = sAb + buf * ABUF;
        const uint32_t sB0 = sBb + buf * BBUF;
        #pragma unroll
        for (int ks = 0; ks < 2; ++ks) {
            uint32_t ah[2][4];
            ldm_x4(ah[0], sA0 + aoff + ks * 32);
            ldm_x4(ah[1], sA0 + aoff + 16 * STR * 2 + ks * 32);
            #pragma unroll
            for (int nt2 = 0; nt2 < 4; ++nt2) {
                uint32_t bh[4];
                ldm_x4(bh, sB0 + boff + nt2 * 16 * STR * 2 + ks * 32);
                #pragma unroll
                for (int mt = 0; mt < 2; ++mt) {
                    mma_fp16(acc[mt][nt2 * 2],     ah[mt], bh);
                    mma_fp16(acc[mt][nt2 * 2 + 1], ah[mt], bh + 2);
                }
            }
        }

        if (pf) {
            __half2 p0 = __floats2half2_rn(v0.x, v0.y);
            __half2 p1 = __floats2half2_rn(v0.z, v0.w);
            __half2 p2 = __floats2half2_rn(v1.x, v1.y);
            __half2 p3 = __floats2half2_rn(v1.z, v1.w);
            *(uint4*)(dsm + nbuf * ABUF + aSts) = make_uint4(
                *(uint32_t*)&p0, *(uint32_t*)&p1, *(uint32_t*)&p2, *(uint32_t*)&p3);
            cp_wait0();
        }
        __syncthreads();
    }

    // ---- epilogue: scale by fw, clip, convert fp16, store ----
    #pragma unroll
    for (int mt = 0; mt < 2; ++mt) {
        int ra = i0 + wm * 32 + mt * 16 + (lane >> 2);
        int rb = ra + 8;
        #pragma unroll
        for (int nt = 0; nt < 8; ++nt) {
            int colg = wn * 64 + nt * 8 + (lane & 3) * 2;
            float f0 = sFW[colg], f1 = sFW[colg + 1];
            if (ra < NN) {
                float vx = fminf(1.f, fmaxf(-1.f, acc[mt][nt][0] * f0));
                float vy = fminf(1.f, fmaxf(-1.f, acc[mt][nt][1] * f1));
                *(__half2*)&g_hh[(size_t)ra * XSTRIDE + g * DG + colg] =
                    __floats2half2_rn(vx, vy);
            }
            if (rb < NN) {
                float vx = fminf(1.f, fmaxf(-1.f, acc[mt][nt][2] * f0));
                float vy = fminf(1.f, fmaxf(-1.f, acc[mt][nt][3] * f1));
                *(__half2*)&g_hh[(size_t)rb * XSTRIDE + g * DG + colg] =
                    __floats2half2_rn(vx, vy);
            }
        }
    }
}

// ---------------------------------------------------------------------------
// Attention v8: PERSISTENT pipelined. Grid 296 (2 blocks/SM), 256 threads.
// Work item = (node pair, group); each block iterates items with stride
// gridDim.x, prefetching item k+1's indices/self/gathers during item k's
// score/softmax/aggregate phases. Indices loaded warp-locally (lane<8 +
// shfl broadcast) -- no smem/sync for them.
// ---------------------------------------------------------------------------
#define ATTN_BLOCKS 296
#define TOTAL_ITEMS NN   // 5000 pairs x 2 groups

__global__ __launch_bounds__(256, 2)
void attn_kernel(const int* __restrict__ graph, float* __restrict__ out) {
    __shared__ float score[2 * KNN];
    __shared__ float agg[8][DG];

    const int t    = threadIdx.x;
    const int lane = t & 31;
    const int w    = t >> 5;
    const int n    = w >> 2;        // node within pair
    const int wl   = w & 3;         // warp within node

    int item = blockIdx.x;

    // ---- prologue: load item 0's indices, self row, gathers ----
    int p = item >> 1, g = item & 1;
    int i0 = p * 2;
    const __half* base = g_hh + g * DG + lane * 8;
    int gidx = 0;
    if (lane < 8)
        gidx = __ldg(&graph[(size_t)(i0 + n) * KNN + wl + 4 * lane]);
    uint4 ovc = *(const uint4*)(base + (size_t)(i0 + n) * XSTRIDE);
    uint4 cur[8];
    #pragma unroll
    for (int r = 0; r < 8; ++r) {
        int idx = __shfl_sync(0xffffffffu, gidx, r);
        cur[r] = __ldcg((const uint4*)(base + (size_t)idx * XSTRIDE));
    }

    for (; item < TOTAL_ITEMS; item += ATTN_BLOCKS) {
        p = item >> 1; g = item & 1; i0 = p * 2;
        const int nxt = item + ATTN_BLOCKS;
        const bool has = nxt < TOTAL_ITEMS;

        // ---- 1. prefetch next item's indices + self row ----
        int gidx_n = 0;
        uint4 ovn = make_uint4(0u, 0u, 0u, 0u);
        const __half* base_n = base;
        if (has) {
            int pn = nxt >> 1, gn = nxt & 1, i0n = pn * 2;
            base_n = g_hh + gn * DG + lane * 8;
            if (lane < 8)
                gidx_n = __ldg(&graph[(size_t)(i0n + n) * KNN + wl + 4 * lane]);
            ovn = __ldcg((const uint4*)(base_n + (size_t)(i0n + n) * XSTRIDE));
        }

        // ---- 2. scores for current item (half2) ----
        const __half2* ov2 = (const __half2*)&ovc;
        #pragma unroll
        for (int r = 0; r < 8; ++r) {
            const __half2* nb2 = (const __half2*)&cur[r];
            __half2 acc2 = __float2half2_rn(0.f);
            #pragma unroll
            for (int d = 0; d < 4; ++d) {
                __half2 df = __hsub2(ov2[d], nb2[d]);
                acc2 = __hfma2(df, df, acc2);
            }
            float2 sf = __half22float2(acc2);
            float s = sf.x + sf.y;
            #pragma unroll
            for (int off = 16; off; off >>= 1)
                s += __shfl_xor_sync(0xffffffffu, s, off);
            if (lane == 0) score[n * KNN + wl + 4 * r] = -s;
        }
        __syncthreads();

        // ---- 3. softmax (warps 0-1: one node each) ----
        if (t < 2 * KNN) {
            float s = score[t];
            float m = s;
            #pragma unroll
            for (int off = 16; off; off >>= 1)
                m = fmaxf(m, __shfl_xor_sync(0xffffffffu, m, off));
            float e = __expf(s - m);
            float sum = e;
            #pragma unroll
            for (int off = 16; off; off >>= 1)
                sum += __shfl_xor_sync(0xffffffffu, sum, off);
            score[t] = e / sum;
        }

        // ---- 4. issue next item's gathers (overlap with aggregate) ----
        uint4 nbuf[8];
        if (has) {
            #pragma unroll
            for (int r = 0; r < 8; ++r) {
                int idx = __shfl_sync(0xffffffffu, gidx_n, r);
                nbuf[r] = __ldcg((const uint4*)(base_n + (size_t)idx * XSTRIDE));
            }
        }
        __syncthreads();

        // ---- 5. weighted aggregate for current item ----
        float acc[8];
        #pragma unroll
        for (int d = 0; d < 8; ++d) acc[d] = 0.f;
        #pragma unroll
        for (int r = 0; r < 8; ++r) {
            float f[8];
            h8_to_f8(cur[r], f);
            float wt = score[n * KNN + wl + 4 * r];
            #pragma unroll
            for (int d = 0; d < 8; ++d)
                acc[d] = fmaf(wt, f[d], acc[d]);
        }
        *(float4*)&agg[w][lane * 8]     = make_float4(acc[0], acc[1], acc[2], acc[3]);
        *(float4*)&agg[w][lane * 8 + 4] = make_float4(acc[4], acc[5], acc[6], acc[7]);
        __syncthreads();

        // ---- 6. cross-warp column sums + store ----
        float s0 = (agg[0][t] + agg[1][t]) + (agg[2][t] + agg[3][t]);
        float s1 = (agg[4][t] + agg[5][t]) + (agg[6][t] + agg[7][t]);
        out[(size_t)i0 * XSTRIDE + g * DG + t] = s0;
        out[(size_t)(i0 + 1) * XSTRIDE + g * DG + t] = s1;

        // ---- 7. rotate buffers ----
        if (has) {
            ovc  = ovn;
            base = base_n;
            #pragma unroll
            for (int r = 0; r < 8; ++r) cur[r] = nbuf[r];
        }
    }
}

// ---------------------------------------------------------------------------
// Launch
// ---------------------------------------------------------------------------
extern "C" void kernel_launch(void* const* d_in, const int* in_sizes, int n_in,
                              void* d_out, int out_size) {
    const float* x     = (const float*)d_in[0];
    const float* W1    = (const float*)d_in[1];
    const float* a1    = (const float*)d_in[2];
    const float* W2    = (const float*)d_in[3];
    const float* a2    = (const float*)d_in[4];
    const int*   graph = (const int*)d_in[5];
    float* out = (float*)d_out;

    static int smem_set = 0;
    if (!smem_set) {
        cudaFuncSetAttribute(gemm_mma_kernel,
                             cudaFuncAttributeMaxDynamicSharedMemorySize, DSM_TOTAL);
        smem_set = 1;
    }

    wcvt_kernel<<<2 * ODIM * DG / (256 * 4), 256>>>(W1, W2);

    dim3 ggrid((NN + 63) / 64, 2);
    gemm_mma_kernel<<<ggrid, 256, DSM_TOTAL>>>(x, a1, a2);

    attn_kernel<<<ATTN_BLOCKS, 256>>>(graph, out);
}

// round 17
// speedup vs baseline: 1.2071x; 1.2071x over previous
#include <cuda_runtime.h>
#include <cuda_bf16.h>
#include <cuda_fp16.h>
#include <cstdint>

// Problem constants (fixed by the reference)
#define NN      10000
#define KNN     32
#define DG      256
#define ODIM    256
#define XSTRIDE 512   // 2*DG

// Scratch: fp16 transformed feature table + fp16 W
__device__ __half g_hh[NN * XSTRIDE];
__device__ __half g_Wh[2 * ODIM * DG];

__device__ __forceinline__ uint32_t smem_u32(const void* p) {
    uint32_t a;
    asm("{ .reg .u64 t; cvta.to.shared.u64 t, %1; cvt.u32.u64 %0, t; }"
        : "=r"(a) : "l"(p));
    return a;
}

__device__ __forceinline__ void ldm_x4(uint32_t* r, uint32_t addr) {
    asm volatile("ldmatrix.sync.aligned.m8n8.x4.shared.b16 {%0,%1,%2,%3}, [%4];"
                 : "=r"(r[0]), "=r"(r[1]), "=r"(r[2]), "=r"(r[3]) : "r"(addr));
}

__device__ __forceinline__ void mma_fp16(float* d, const uint32_t* a,
                                         const uint32_t* b) {
    asm volatile(
        "mma.sync.aligned.m16n8k16.row.col.f32.f16.f16.f32 "
        "{%0,%1,%2,%3}, {%4,%5,%6,%7}, {%8,%9}, {%0,%1,%2,%3};"
        : "+f"(d[0]), "+f"(d[1]), "+f"(d[2]), "+f"(d[3])
        : "r"(a[0]), "r"(a[1]), "r"(a[2]), "r"(a[3]), "r"(b[0]), "r"(b[1]));
}

__device__ __forceinline__ void cp_async16(uint32_t smem, const void* gptr) {
    asm volatile("cp.async.cg.shared.global [%0], [%1], 16;"
                 :: "r"(smem), "l"(gptr) : "memory");
}
__device__ __forceinline__ void cp_commit() {
    asm volatile("cp.async.commit_group;" ::: "memory");
}
__device__ __forceinline__ void cp_wait0() {
    asm volatile("cp.async.wait_group 0;" ::: "memory");
}

// unpack 8 halves (uint4) into 8 floats
__device__ __forceinline__ void h8_to_f8(uint4 u, float* f) {
    float2 p;
    p = __half22float2(*(__half2*)&u.x); f[0] = p.x; f[1] = p.y;
    p = __half22float2(*(__half2*)&u.y); f[2] = p.x; f[3] = p.y;
    p = __half22float2(*(__half2*)&u.z); f[4] = p.x; f[5] = p.y;
    p = __half22float2(*(__half2*)&u.w); f[6] = p.x; f[7] = p.y;
}

// ---------------------------------------------------------------------------
// Kernel 0: convert W1/W2 to fp16.
// ---------------------------------------------------------------------------
__global__ __launch_bounds__(256)
void wcvt_kernel(const float* __restrict__ W1, const float* __restrict__ W2) {
    int idx = blockIdx.x * 256 + threadIdx.x;
    int wlin = idx * 4;
    int g = wlin >= ODIM * DG;
    int off = wlin - g * ODIM * DG;
    const float* __restrict__ W = g ? W2 : W1;
    float4 v = *(const float4*)&W[off];
    __half2 p0 = __floats2half2_rn(v.x, v.y);
    __half2 p1 = __floats2half2_rn(v.z, v.w);
    *(uint2*)&g_Wh[wlin] = make_uint2(*(uint32_t*)&p0, *(uint32_t*)&p1);
}

// ---------------------------------------------------------------------------
// GEMM via HMMA fp16 (proven R13): 64x256 tile, software-pipelined fills,
// 8 warps (2m x 4n). Grid (157, 2). Epilogue -> fp16 table.
// ---------------------------------------------------------------------------
#define STR 40   // fp16 per smem row (32 k + 8 pad): 80B stride, conflict-free

#define ABUF      (64 * STR * 2)                 // 5120
#define BBUF      (256 * STR * 2)                // 20480
#define DSM_A     0                               // 2 x ABUF
#define DSM_B     (2 * ABUF)                      // 10240, 2 x BBUF
#define DSM_FW    (DSM_B + 2 * BBUF)              // 51200
#define DSM_RED   (DSM_FW + 1024)                 // 52224
#define DSM_TOTAL (DSM_RED + 1024)                // 53248

__global__ __launch_bounds__(256)
void gemm_mma_kernel(const float* __restrict__ x,
                     const float* __restrict__ a1, const float* __restrict__ a2) {
    extern __shared__ char dsm[];
    float* sFW = (float*)(dsm + DSM_FW);
    float* red = (float*)(dsm + DSM_RED);

    const int t    = threadIdx.x;
    const int lane = t & 31;
    const int wid  = t >> 5;
    const int wm   = wid >> 2;     // 0..1
    const int wn   = wid & 3;      // 0..3
    const int g    = blockIdx.y;
    const int i0   = blockIdx.x * 64;
    const float* __restrict__ a = g ? a2 : a1;
    const __half* __restrict__ Wh = g_Wh + g * ODIM * DG;

    // ---- fused fw = softmax(a) ----
    float av = a[t];
    red[t] = av; __syncthreads();
    #pragma unroll
    for (int s = 128; s > 0; s >>= 1) {
        if (t < s) red[t] = fmaxf(red[t], red[t + s]);
        __syncthreads();
    }
    float amax = red[0]; __syncthreads();
    float e = expf(av - amax);
    red[t] = e; __syncthreads();
    #pragma unroll
    for (int s = 128; s > 0; s >>= 1) {
        if (t < s) red[t] += red[t + s];
        __syncthreads();
    }
    float esum = red[0]; __syncthreads();
    sFW[t] = e / esum;

    const uint32_t sAb = smem_u32(dsm + DSM_A);
    const uint32_t sBb = smem_u32(dsm + DSM_B);
    const uint32_t aoff = (uint32_t)(((wm * 32 + (lane & 15)) * STR +
                                      ((lane >> 4) & 1) * 8) * 2);
    const uint32_t boff = (uint32_t)(((wn * 64 + (lane & 7) + ((lane >> 4) & 1) * 8) * STR +
                                      ((lane >> 3) & 1) * 8) * 2);

    float acc[2][8][4];
    #pragma unroll
    for (int mt = 0; mt < 2; ++mt)
        #pragma unroll
        for (int nt = 0; nt < 8; ++nt)
            #pragma unroll
            for (int q = 0; q < 4; ++q) acc[mt][nt][q] = 0.f;

    const int arow = t >> 2;
    const int akk  = (t & 3) * 8;
    const bool arow_ok = (i0 + arow) < NN;
    const float* __restrict__ xrow =
        x + (size_t)(i0 + arow) * XSTRIDE + g * DG + akk;
    const uint32_t aSts = (uint32_t)((arow * STR + akk) * 2);

    int brow[4], bkk[4];
    #pragma unroll
    for (int q = 0; q < 4; ++q) {
        int lin = q * 256 + t;
        brow[q] = lin >> 2;
        bkk[q]  = (lin & 3) * 8;
    }

    // ---- prologue: stage chunk 0 ----
    {
        #pragma unroll
        for (int q = 0; q < 4; ++q)
            cp_async16(sBb + (uint32_t)((brow[q] * STR + bkk[q]) * 2),
                       &Wh[(size_t)brow[q] * DG + bkk[q]]);
        cp_commit();
        float4 v0 = make_float4(0.f, 0.f, 0.f, 0.f);
        float4 v1 = make_float4(0.f, 0.f, 0.f, 0.f);
        if (arow_ok) {
            v0 = *(const float4*)(xrow);
            v1 = *(const float4*)(xrow + 4);
        }
        __half2 p0 = __floats2half2_rn(v0.x, v0.y);
        __half2 p1 = __floats2half2_rn(v0.z, v0.w);
        __half2 p2 = __floats2half2_rn(v1.x, v1.y);
        __half2 p3 = __floats2half2_rn(v1.z, v1.w);
        *(uint4*)(dsm + aSts) = make_uint4(
            *(uint32_t*)&p0, *(uint32_t*)&p1, *(uint32_t*)&p2, *(uint32_t*)&p3);
        cp_wait0();
    }
    __syncthreads();

    for (int c = 0; c < 8; ++c) {
        const int buf  = c & 1;
        const int nbuf = buf ^ 1;
        const bool pf = c < 7;
        float4 v0, v1;

        if (pf) {
            const int kn = (c + 1) * 32;
            #pragma unroll
            for (int q = 0; q < 4; ++q)
                cp_async16(sBb + (uint32_t)(nbuf * BBUF + (brow[q] * STR + bkk[q]) * 2),
                           &Wh[(size_t)brow[q] * DG + kn + bkk[q]]);
            cp_commit();
            if (arow_ok) {
                v0 = *(const float4*)(xrow + kn);
                v1 = *(const float4*)(xrow + kn + 4);
            } else {
                v0 = make_float4(0.f, 0.f, 0.f, 0.f);
                v1 = make_float4(0.f, 0.f, 0.f, 0.f);
            }
        }

        const uint32_t sA0 = sAb + buf * ABUF;
        const uint32_t sB0 = sBb + buf * BBUF;
        #pragma unroll
        for (int ks = 0; ks < 2; ++ks) {
            uint32_t ah[2][4];
            ldm_x4(ah[0], sA0 + aoff + ks * 32);
            ldm_x4(ah[1], sA0 + aoff + 16 * STR * 2 + ks * 32);
            #pragma unroll
            for (int nt2 = 0; nt2 < 4; ++nt2) {
                uint32_t bh[4];
                ldm_x4(bh, sB0 + boff + nt2 * 16 * STR * 2 + ks * 32);
                #pragma unroll
                for (int mt = 0; mt < 2; ++mt) {
                    mma_fp16(acc[mt][nt2 * 2],     ah[mt], bh);
                    mma_fp16(acc[mt][nt2 * 2 + 1], ah[mt], bh + 2);
                }
            }
        }

        if (pf) {
            __half2 p0 = __floats2half2_rn(v0.x, v0.y);
            __half2 p1 = __floats2half2_rn(v0.z, v0.w);
            __half2 p2 = __floats2half2_rn(v1.x, v1.y);
            __half2 p3 = __floats2half2_rn(v1.z, v1.w);
            *(uint4*)(dsm + nbuf * ABUF + aSts) = make_uint4(
                *(uint32_t*)&p0, *(uint32_t*)&p1, *(uint32_t*)&p2, *(uint32_t*)&p3);
            cp_wait0();
        }
        __syncthreads();
    }

    // ---- epilogue: scale by fw, clip, convert fp16, store ----
    #pragma unroll
    for (int mt = 0; mt < 2; ++mt) {
        int ra = i0 + wm * 32 + mt * 16 + (lane >> 2);
        int rb = ra + 8;
        #pragma unroll
        for (int nt = 0; nt < 8; ++nt) {
            int colg = wn * 64 + nt * 8 + (lane & 3) * 2;
            float f0 = sFW[colg], f1 = sFW[colg + 1];
            if (ra < NN) {
                float vx = fminf(1.f, fmaxf(-1.f, acc[mt][nt][0] * f0));
                float vy = fminf(1.f, fmaxf(-1.f, acc[mt][nt][1] * f1));
                *(__half2*)&g_hh[(size_t)ra * XSTRIDE + g * DG + colg] =
                    __floats2half2_rn(vx, vy);
            }
            if (rb < NN) {
                float vx = fminf(1.f, fmaxf(-1.f, acc[mt][nt][2] * f0));
                float vy = fminf(1.f, fmaxf(-1.f, acc[mt][nt][3] * f1));
                *(__half2*)&g_hh[(size_t)rb * XSTRIDE + g * DG + colg] =
                    __floats2half2_rn(vx, vy);
            }
        }
    }
}

// ---------------------------------------------------------------------------
// Attention v6.1: 2 nodes per block (grid 5000 x 2), 256 threads.
// Warp w serves node (w>>2); 8 neighbor rows per warp (MLP=8, raw fp16),
// half2 scoring. NEW vs v6: graph indices loaded WARP-LOCALLY (lane<8 LDG +
// shfl broadcast) -- removes the idxs smem round-trip and the block's first
// __syncthreads, so each warp issues its gathers immediately on entry.
// ---------------------------------------------------------------------------
__global__ __launch_bounds__(256)
void attn_kernel(const int* __restrict__ graph, float* __restrict__ out) {
    const int i0 = blockIdx.x * 2;
    const int g  = blockIdx.y;

    __shared__ float score[2 * KNN];
    __shared__ float agg[8][DG];    // rows 0-3: node 0, rows 4-7: node 1

    const int t    = threadIdx.x;
    const int lane = t & 31;
    const int w    = t >> 5;
    const int n    = w >> 2;        // node within pair
    const int wl   = w & 3;         // warp within node

    // warp-local graph indices: lane r<8 loads index of neighbor wl+4r
    int gidx = 0;
    if (lane < 8)
        gidx = __ldg(&graph[(size_t)(i0 + n) * KNN + wl + 4 * lane]);

    const __half* __restrict__ base = g_hh + g * DG + lane * 8;

    // self row (raw fp16)
    uint4 ovu = *(const uint4*)(base + (size_t)(i0 + n) * XSTRIDE);
    const __half2* ov2 = (const __half2*)&ovu;

    // gather 8 neighbor rows (512B contiguous each, MLP=8) -- no barrier first
    uint4 nbu[8];
    #pragma unroll
    for (int r = 0; r < 8; ++r) {
        int idx = __shfl_sync(0xffffffffu, gidx, r);
        nbu[r] = __ldcg((const uint4*)(base + (size_t)idx * XSTRIDE));
    }

    // scores in half2
    #pragma unroll
    for (int r = 0; r < 8; ++r) {
        const __half2* nb2 = (const __half2*)&nbu[r];
        __half2 acc2 = __float2half2_rn(0.f);
        #pragma unroll
        for (int d = 0; d < 4; ++d) {
            __half2 df = __hsub2(ov2[d], nb2[d]);
            acc2 = __hfma2(df, df, acc2);
        }
        float2 sf = __half22float2(acc2);
        float s = sf.x + sf.y;
        #pragma unroll
        for (int off = 16; off; off >>= 1) s += __shfl_xor_sync(0xffffffffu, s, off);
        if (lane == 0) score[n * KNN + wl + 4 * r] = -s;
    }
    __syncthreads();

    // softmax: warp 0 -> node 0, warp 1 -> node 1
    if (t < 2 * KNN) {
        float s = score[t];
        float m = s;
        #pragma unroll
        for (int off = 16; off; off >>= 1) m = fmaxf(m, __shfl_xor_sync(0xffffffffu, m, off));
        float e = __expf(s - m);
        float sum = e;
        #pragma unroll
        for (int off = 16; off; off >>= 1) sum += __shfl_xor_sync(0xffffffffu, sum, off);
        score[t] = e / sum;
    }
    __syncthreads();

    // weighted partial aggregate (fp32)
    float acc[8];
    #pragma unroll
    for (int d = 0; d < 8; ++d) acc[d] = 0.f;
    #pragma unroll
    for (int r = 0; r < 8; ++r) {
        float f[8];
        h8_to_f8(nbu[r], f);
        float wt = score[n * KNN + wl + 4 * r];
        #pragma unroll
        for (int d = 0; d < 8; ++d)
            acc[d] = fmaf(wt, f[d], acc[d]);
    }
    *(float4*)&agg[w][lane * 8]     = make_float4(acc[0], acc[1], acc[2], acc[3]);
    *(float4*)&agg[w][lane * 8 + 4] = make_float4(acc[4], acc[5], acc[6], acc[7]);
    __syncthreads();

    // cross-warp column sums + store (thread t = column t, both nodes)
    float s0 = (agg[0][t] + agg[1][t]) + (agg[2][t] + agg[3][t]);
    float s1 = (agg[4][t] + agg[5][t]) + (agg[6][t] + agg[7][t]);
    out[(size_t)i0 * XSTRIDE + g * DG + t] = s0;
    out[(size_t)(i0 + 1) * XSTRIDE + g * DG + t] = s1;
}

// ---------------------------------------------------------------------------
// Launch
// ---------------------------------------------------------------------------
extern "C" void kernel_launch(void* const* d_in, const int* in_sizes, int n_in,
                              void* d_out, int out_size) {
    const float* x     = (const float*)d_in[0];
    const float* W1    = (const float*)d_in[1];
    const float* a1    = (const float*)d_in[2];
    const float* W2    = (const float*)d_in[3];
    const float* a2    = (const float*)d_in[4];
    const int*   graph = (const int*)d_in[5];
    float* out = (float*)d_out;

    static int smem_set = 0;
    if (!smem_set) {
        cudaFuncSetAttribute(gemm_mma_kernel,
                             cudaFuncAttributeMaxDynamicSharedMemorySize, DSM_TOTAL);
        smem_set = 1;
    }

    wcvt_kernel<<<2 * ODIM * DG / (256 * 4), 256>>>(W1, W2);

    dim3 ggrid((NN + 63) / 64, 2);
    gemm_mma_kernel<<<ggrid, 256, DSM_TOTAL>>>(x, a1, a2);

    dim3 agrid(NN / 2, 2);
    attn_kernel<<<agrid, 256>>>(graph, out);
}